// round 6
// baseline (speedup 1.0000x reference)
#include <cuda_runtime.h>
#include <cuda_fp16.h>
#include <cuda_bf16.h>

#define NN 100000
#define EE 3200000
#define IND 81
#define HID 64
#define LAT 32
#define BN_EPS 1e-5f
#define SCAN_BLK 1024
#define STATS_BLOCKS 512

// Scratch (device globals; no allocation allowed)
__device__ __align__(128) __half2 g_half[NN * 32];   // fp16 Hs rows (aggregate input)
__device__ __align__(128) float g_bufA[NN * HID];    // reused as fp16 aggregate output
__device__ __align__(128) float g_bufB[NN * HID];    // reused as BN partials
__device__ float g_dis[NN];
__device__ int   g_cnt[NN];
__device__ int   g_rowptr[NN + 1];
__device__ int   g_cursor[NN + 1];
__device__ int   g_csr[EE];
__device__ int   g_bsums[(NN + SCAN_BLK - 1) / SCAN_BLK + 1];
__device__ float g_stats[128];   // scale[64], shift[64] after reduce

// ---------------------------------------------------------------------------
__device__ __forceinline__ bool edges_are_i64(const void* ei) {
    long long v0 = ((const long long*)ei)[0];
    return (v0 >= 0 && v0 < 1000000LL);
}
__device__ __forceinline__ int edge_at(const void* ei, bool is64, int i) {
    return is64 ? (int)((const long long*)ei)[i] : ((const int*)ei)[i];
}
__device__ __forceinline__ float2 h2f(unsigned u) {
    __half2 h = *reinterpret_cast<__half2*>(&u);
    return __half22float2(h);
}
__device__ __forceinline__ unsigned f2h(float a, float b) {
    __half2 h = __floats2half2_rn(a, b);
    return *reinterpret_cast<unsigned*>(&h);
}

// ---------------------------------------------------------------------------
__global__ void zero_cnt(int* cnt, int n) {
    int i = blockIdx.x * blockDim.x + threadIdx.x;
    if (i < n) cnt[i] = 0;
}

__global__ void hist_dst(const void* ei, int* cnt, int E) {
    int e = blockIdx.x * blockDim.x + threadIdx.x;
    if (e >= E) return;
    bool is64 = edges_are_i64(ei);
    int d = edge_at(ei, is64, E + e);
    atomicAdd(&cnt[d], 1);
}

__global__ void scan1(const int* __restrict__ cnt, int* __restrict__ rowptr,
                      int* __restrict__ bsums, int n) {
    __shared__ int s[SCAN_BLK];
    int t = threadIdx.x;
    int i = blockIdx.x * SCAN_BLK + t;
    int val = (i < n) ? cnt[i] : 0;
    s[t] = val;
    __syncthreads();
    for (int off = 1; off < SCAN_BLK; off <<= 1) {
        int x = (t >= off) ? s[t - off] : 0;
        __syncthreads();
        s[t] += x;
        __syncthreads();
    }
    if (i < n) rowptr[i + 1] = s[t];
    if (t == SCAN_BLK - 1) bsums[blockIdx.x] = s[t];
}

__global__ void scan2(int* bsums, int nb) {
    __shared__ int s[SCAN_BLK];
    int t = threadIdx.x;
    int v = (t < nb) ? bsums[t] : 0;
    s[t] = v;
    __syncthreads();
    for (int off = 1; off < SCAN_BLK; off <<= 1) {
        int x = (t >= off) ? s[t - off] : 0;
        __syncthreads();
        s[t] += x;
        __syncthreads();
    }
    if (t < nb) bsums[t] = s[t] - v;   // exclusive
}

__global__ void scan3(int* __restrict__ rowptr, int* __restrict__ cursor,
                      const int* __restrict__ bsums, const int* __restrict__ cnt,
                      float* __restrict__ dis, int n) {
    int i = blockIdx.x * blockDim.x + threadIdx.x;
    if (i == 0) { rowptr[0] = 0; cursor[0] = 0; }
    if (i < n) {
        int v = rowptr[i + 1] + bsums[i / SCAN_BLK];
        rowptr[i + 1] = v;
        cursor[i + 1] = v;
        dis[i] = rsqrtf((float)(cnt[i] + 1));
    }
}

__global__ void scatter_csr(const void* ei, int* __restrict__ cursor,
                            int* __restrict__ csr, int E) {
    int e = blockIdx.x * blockDim.x + threadIdx.x;
    if (e >= E) return;
    bool is64 = edges_are_i64(ei);
    int s = edge_at(ei, is64, e);
    int d = edge_at(ei, is64, E + e);
    int pos = atomicAdd(&cursor[d], 1);
    csr[pos] = s;
}

// ---------------------------------------------------------------------------
// GEMM: Yh[N,64] = half((X[N,81] @ W[81,64]) * dis[n])
__global__ void gemm81_dis(const float* __restrict__ X, const float* __restrict__ W,
                           const float* __restrict__ dis, __half* __restrict__ Yh, int N) {
    __shared__ float Ws[IND * HID];
    __shared__ float Xs[16][IND];
    int tx = threadIdx.x;
    int ty = threadIdx.y;
    int tid = ty * 64 + tx;
    for (int i = tid; i < IND * HID; i += 256) Ws[i] = W[i];
    int n0 = blockIdx.x * 16;
    for (int i = tid; i < 16 * IND; i += 256) {
        int r = i / IND, c = i % IND;
        int n = n0 + r;
        Xs[r][c] = (n < N) ? X[n * IND + c] : 0.0f;
    }
    __syncthreads();
    float acc[4] = {0.f, 0.f, 0.f, 0.f};
    for (int k = 0; k < IND; ++k) {
        float w = Ws[k * HID + tx];
        #pragma unroll
        for (int r = 0; r < 4; ++r) acc[r] += Xs[ty * 4 + r][k] * w;
    }
    #pragma unroll
    for (int r = 0; r < 4; ++r) {
        int n = n0 + ty * 4 + r;
        if (n < N) Yh[n * HID + tx] = __float2half(acc[r] * __ldg(&dis[n]));
    }
}

// GEMM, fp16 input with fused BN+ReLU: Yh = half((relu(bn(Xh)) @ W) * dis[n])
__global__ void gemm64_bn_dis_h(const __half2* __restrict__ Xh, const float* __restrict__ W,
                                const float* __restrict__ stats, const float* __restrict__ dis,
                                __half* __restrict__ Yh, int N) {
    __shared__ float Ws[HID * HID];
    __shared__ float Xs[16][HID];
    __shared__ float sc[64], sh[64];
    int tx = threadIdx.x;
    int ty = threadIdx.y;
    int tid = ty * 64 + tx;
    for (int i = tid; i < HID * HID; i += 256) Ws[i] = W[i];
    if (tid < 64) { sc[tid] = stats[tid]; sh[tid] = stats[64 + tid]; }
    int n0 = blockIdx.x * 16;
    __syncthreads();
    for (int i = tid; i < 16 * 32; i += 256) {   // 16 rows x 32 half2
        int r = i >> 5, c2 = i & 31;
        int n = n0 + r;
        float2 v = (n < N) ? __half22float2(Xh[n * 32 + c2]) : make_float2(0.f, 0.f);
        int c = 2 * c2;
        Xs[r][c]     = fmaxf(fmaf(v.x, sc[c], sh[c]), 0.0f);
        Xs[r][c + 1] = fmaxf(fmaf(v.y, sc[c + 1], sh[c + 1]), 0.0f);
    }
    __syncthreads();
    float acc[4] = {0.f, 0.f, 0.f, 0.f};
    for (int k = 0; k < HID; ++k) {
        float w = Ws[k * HID + tx];
        #pragma unroll
        for (int r = 0; r < 4; ++r) acc[r] += Xs[ty * 4 + r][k] * w;
    }
    #pragma unroll
    for (int r = 0; r < 4; ++r) {
        int n = n0 + ty * 4 + r;
        if (n < N) Yh[n * HID + tx] = __float2half(acc[r] * __ldg(&dis[n]));
    }
}

// Final heads (fp16 input, fp32 output)
__global__ void gemm_mu_ls_h(const __half2* __restrict__ Xh,
                             const float* __restrict__ Wmu, const float* __restrict__ bmu,
                             const float* __restrict__ Wls, const float* __restrict__ bls,
                             float* __restrict__ out, int N) {
    __shared__ float Ws[HID * 64];
    __shared__ float bs[64];
    __shared__ float Xs[16][HID];
    int tx = threadIdx.x;
    int ty = threadIdx.y;
    int tid = ty * 64 + tx;
    for (int i = tid; i < HID * 64; i += 256) {
        int k = i >> 6, f = i & 63;
        Ws[i] = (f < LAT) ? Wmu[k * LAT + f] : Wls[k * LAT + (f - LAT)];
    }
    if (tid < 64) bs[tid] = (tid < LAT) ? bmu[tid] : bls[tid - LAT];
    int n0 = blockIdx.x * 16;
    for (int i = tid; i < 16 * 32; i += 256) {
        int r = i >> 5, c2 = i & 31;
        int n = n0 + r;
        float2 v = (n < N) ? __half22float2(Xh[n * 32 + c2]) : make_float2(0.f, 0.f);
        Xs[r][2 * c2] = v.x;
        Xs[r][2 * c2 + 1] = v.y;
    }
    __syncthreads();
    float acc[4] = {0.f, 0.f, 0.f, 0.f};
    for (int k = 0; k < HID; ++k) {
        float w = Ws[k * 64 + tx];
        #pragma unroll
        for (int r = 0; r < 4; ++r) acc[r] += Xs[ty * 4 + r][k] * w;
    }
    int f = tx & (LAT - 1);
    long long off = (tx < LAT) ? 0 : (long long)N * LAT;
    #pragma unroll
    for (int r = 0; r < 4; ++r) {
        int n = n0 + ty * 4 + r;
        if (n < N) out[off + (long long)n * LAT + f] = acc[r] + bs[tx];
    }
}

// ---------------------------------------------------------------------------
// Aggregation, 4 nodes per warp: 8-lane groups; each lane loads 16 B (8 feats).
// out[n] = half((sum_{s in nbr(n)} Hs[s] + Hs[n]) * dis[n] + b)
__global__ void aggregate4(const uint4* __restrict__ Hr, const int* __restrict__ rowptr,
                           const int* __restrict__ csr, const float* __restrict__ dis,
                           const float* __restrict__ bias, uint4* __restrict__ outH, int N) {
    int warp = (blockIdx.x * blockDim.x + threadIdx.x) >> 5;
    int lane = threadIdx.x & 31;
    int grp = lane >> 3;           // 0..3
    int sub = lane & 7;            // handles feats 8*sub .. 8*sub+7
    int n = warp * 4 + grp;
    if (n >= N) return;

    uint4 raw = __ldg(&Hr[n * 8 + sub]);
    float2 p0 = h2f(raw.x), p1 = h2f(raw.y), p2 = h2f(raw.z), p3 = h2f(raw.w);
    float c0 = p0.x, c1 = p0.y, c2 = p1.x, c3 = p1.y;
    float c4 = p2.x, c5 = p2.y, c6 = p3.x, c7 = p3.y;
    float d0 = 0.f, d1 = 0.f, d2 = 0.f, d3 = 0.f;
    float d4 = 0.f, d5 = 0.f, d6 = 0.f, d7 = 0.f;

    int j = __ldg(&rowptr[n]);
    int end = __ldg(&rowptr[n + 1]);
    for (; j + 2 <= end; j += 2) {
        int t0 = __ldg(&csr[j]);
        int t1 = __ldg(&csr[j + 1]);
        uint4 r0 = __ldg(&Hr[t0 * 8 + sub]);
        uint4 r1 = __ldg(&Hr[t1 * 8 + sub]);
        float2 v;
        v = h2f(r0.x); c0 += v.x; c1 += v.y;
        v = h2f(r0.y); c2 += v.x; c3 += v.y;
        v = h2f(r0.z); c4 += v.x; c5 += v.y;
        v = h2f(r0.w); c6 += v.x; c7 += v.y;
        v = h2f(r1.x); d0 += v.x; d1 += v.y;
        v = h2f(r1.y); d2 += v.x; d3 += v.y;
        v = h2f(r1.z); d4 += v.x; d5 += v.y;
        v = h2f(r1.w); d6 += v.x; d7 += v.y;
    }
    if (j < end) {
        int t0 = __ldg(&csr[j]);
        uint4 r0 = __ldg(&Hr[t0 * 8 + sub]);
        float2 v;
        v = h2f(r0.x); c0 += v.x; c1 += v.y;
        v = h2f(r0.y); c2 += v.x; c3 += v.y;
        v = h2f(r0.z); c4 += v.x; c5 += v.y;
        v = h2f(r0.w); c6 += v.x; c7 += v.y;
    }

    float dd = __ldg(&dis[n]);
    float4 bA = make_float4(0.f, 0.f, 0.f, 0.f);
    float4 bB = make_float4(0.f, 0.f, 0.f, 0.f);
    if (bias) {
        bA = ((const float4*)bias)[sub * 2];
        bB = ((const float4*)bias)[sub * 2 + 1];
    }
    uint4 o;
    o.x = f2h(fmaf(c0 + d0, dd, bA.x), fmaf(c1 + d1, dd, bA.y));
    o.y = f2h(fmaf(c2 + d2, dd, bA.z), fmaf(c3 + d3, dd, bA.w));
    o.z = f2h(fmaf(c4 + d4, dd, bB.x), fmaf(c5 + d5, dd, bB.y));
    o.w = f2h(fmaf(c6 + d6, dd, bB.z), fmaf(c7 + d7, dd, bB.w));
    outH[n * 8 + sub] = o;
}

// ---------------------------------------------------------------------------
// BN stats on fp16 input: per-block partials (no atomics). partial[blk*128 + 0..63]
// = sum per feature, [64..127] = sumsq per feature.
__global__ void bn_stats_h(const __half2* __restrict__ H, float* __restrict__ partial, int N) {
    int tid = threadIdx.x;        // 256
    int c2 = tid & 31;
    int rg = tid >> 5;            // 0..7
    int r = blockIdx.x * 8 + rg;
    int stride = gridDim.x * 8;
    float sx = 0.f, sy = 0.f, qx = 0.f, qy = 0.f;
    for (; r < N; r += stride) {
        float2 v = __half22float2(H[r * 32 + c2]);
        sx += v.x; sy += v.y;
        qx += v.x * v.x; qy += v.y * v.y;
    }
    __shared__ float4 red[256];
    red[tid] = make_float4(sx, sy, qx, qy);
    __syncthreads();
    if (tid < 32) {
        float4 t = red[tid];
        #pragma unroll
        for (int w = 1; w < 8; ++w) {
            float4 u = red[w * 32 + tid];
            t.x += u.x; t.y += u.y; t.z += u.z; t.w += u.w;
        }
        float* p = partial + blockIdx.x * 128;
        p[2 * tid]      = t.x;
        p[2 * tid + 1]  = t.y;
        p[64 + 2 * tid]     = t.z;
        p[64 + 2 * tid + 1] = t.w;
    }
}

// Reduce partials + finalize scale/shift. 128 threads, grid 1.
__global__ void bn_reduce(const float* __restrict__ partial, float* __restrict__ stats,
                          const float* __restrict__ g, const float* __restrict__ beta,
                          int nb, int N) {
    __shared__ float acc[128];
    int tid = threadIdx.x;
    float s = 0.f;
    #pragma unroll 8
    for (int b = 0; b < nb; ++b) s += partial[b * 128 + tid];
    acc[tid] = s;
    __syncthreads();
    if (tid < 64) {
        float invN = 1.0f / (float)N;
        float m = acc[tid] * invN;
        float v = acc[64 + tid] * invN - m * m;
        float scale = g[tid] * rsqrtf(v + BN_EPS);
        stats[tid] = scale;
        stats[64 + tid] = beta[tid] - m * scale;
    }
}

// Hs[n] = half(relu(bn(in[n])) * dis[n]) ; fp16 -> fp16
__global__ void bn_relu_dis_h(const __half2* __restrict__ H, const float* __restrict__ stats,
                              const float* __restrict__ dis, __half2* __restrict__ out, int total2) {
    int idx = blockIdx.x * blockDim.x + threadIdx.x;
    if (idx >= total2) return;
    int c2 = idx & 31;
    int n = idx >> 5;
    float2 v = __half22float2(H[idx]);
    int c = 2 * c2;
    float dd = __ldg(&dis[n]);
    float yx = fmaxf(fmaf(v.x, __ldg(&stats[c]), __ldg(&stats[64 + c])), 0.0f) * dd;
    float yy = fmaxf(fmaf(v.y, __ldg(&stats[c + 1]), __ldg(&stats[64 + c + 1])), 0.0f) * dd;
    out[idx] = __floats2half2_rn(yx, yy);
}

// ---------------------------------------------------------------------------
extern "C" void kernel_launch(void* const* d_in, const int* in_sizes, int n_in,
                              void* d_out, int out_size) {
    const float* x    = (const float*)d_in[0];
    const void*  ei   = d_in[1];
    const float* W1   = (const float*)d_in[2];
    const float* b1   = (const float*)d_in[3];
    const float* g1   = (const float*)d_in[4];
    const float* be1  = (const float*)d_in[5];
    const float* W2   = (const float*)d_in[6];
    const float* b2   = (const float*)d_in[7];
    const float* g2   = (const float*)d_in[8];
    const float* be2  = (const float*)d_in[9];
    const float* Wmu  = (const float*)d_in[10];
    const float* bmu  = (const float*)d_in[11];
    const float* Wls  = (const float*)d_in[12];
    const float* bls  = (const float*)d_in[13];
    float* out = (float*)d_out;

    int N = in_sizes[0] / IND;
    int E = in_sizes[1] / 2;

    float *pA, *pB, *pDis, *pStats;
    __half2* pH;
    int *pCnt, *pRow, *pCur, *pCsr, *pBs;
    cudaGetSymbolAddress((void**)&pA, g_bufA);
    cudaGetSymbolAddress((void**)&pB, g_bufB);
    cudaGetSymbolAddress((void**)&pDis, g_dis);
    cudaGetSymbolAddress((void**)&pStats, g_stats);
    cudaGetSymbolAddress((void**)&pH, g_half);
    cudaGetSymbolAddress((void**)&pCnt, g_cnt);
    cudaGetSymbolAddress((void**)&pRow, g_rowptr);
    cudaGetSymbolAddress((void**)&pCur, g_cursor);
    cudaGetSymbolAddress((void**)&pCsr, g_csr);
    cudaGetSymbolAddress((void**)&pBs, g_bsums);

    __half2* pGh = (__half2*)pA;     // fp16 aggregate output
    float* pPart = pB;               // BN partials (512*128 floats)

    int nScanBlocks = (N + SCAN_BLK - 1) / SCAN_BLK;
    dim3 gThr(64, 4);
    int gemmGrid = (N + 15) / 16;
    int aggGrid = ((N + 3) / 4 + 7) / 8;   // 4 nodes/warp, 8 warps/block = 32 nodes/block
    int total2 = N * 32;

    // 1. CSR build + normalization
    zero_cnt<<<(N + 255) / 256, 256>>>(pCnt, N);
    hist_dst<<<(E + 255) / 256, 256>>>(ei, pCnt, E);
    scan1<<<nScanBlocks, SCAN_BLK>>>(pCnt, pRow, pBs, N);
    scan2<<<1, SCAN_BLK>>>(pBs, nScanBlocks);
    scan3<<<(N + 255) / 256, 256>>>(pRow, pCur, pBs, pCnt, pDis, N);
    scatter_csr<<<(E + 255) / 256, 256>>>(ei, pCur, pCsr, E);

    // 2. conv1
    gemm81_dis<<<gemmGrid, gThr>>>(x, W1, pDis, (__half*)pH, N);
    aggregate4<<<aggGrid, 256>>>((const uint4*)pH, pRow, pCsr, pDis, b1, (uint4*)pGh, N);

    // 3. BN1 stats (two-stage, no atomics)
    bn_stats_h<<<STATS_BLOCKS, 256>>>(pGh, pPart, N);
    bn_reduce<<<1, 128>>>(pPart, pStats, g1, be1, STATS_BLOCKS, N);

    // 4. conv2 (BN1 apply + ReLU fused into GEMM input)
    gemm64_bn_dis_h<<<gemmGrid, gThr>>>(pGh, W2, pStats, pDis, (__half*)pH, N);
    aggregate4<<<aggGrid, 256>>>((const uint4*)pH, pRow, pCsr, pDis, b2, (uint4*)pGh, N);

    // 5. BN2 stats
    bn_stats_h<<<STATS_BLOCKS, 256>>>(pGh, pPart, N);
    bn_reduce<<<1, 128>>>(pPart, pStats, g2, be2, STATS_BLOCKS, N);

    // 6. Hs = relu(bn(.)) * dis ; shared aggregation for both heads
    bn_relu_dis_h<<<(total2 + 255) / 256, 256>>>(pGh, pStats, pDis, pH, total2);
    aggregate4<<<aggGrid, 256>>>((const uint4*)pH, pRow, pCsr, pDis, (const float*)nullptr,
                                 (uint4*)pGh, N);

    // 7. heads
    gemm_mu_ls_h<<<gemmGrid, gThr>>>(pGh, Wmu, bmu, Wls, bls, out, N);
}

// round 7
// speedup vs baseline: 1.0093x; 1.0093x over previous
#include <cuda_runtime.h>
#include <cuda_fp16.h>
#include <cuda_bf16.h>

#define NN 100000
#define EE 3200000
#define IND 81
#define HID 64
#define LAT 32
#define BN_EPS 1e-5f
#define SCAN_BLK 1024
#define STATS_BLOCKS 512

// Scratch (device globals; no allocation allowed)
__device__ __align__(128) __half2 g_half[NN * 32];   // fp16 Hs rows (aggregate input)
__device__ __align__(128) float g_bufA[NN * HID];    // reused: fp16 aggregate output
__device__ __align__(128) float g_bufB[NN * HID];    // reused: BN partials
__device__ float g_dis[NN];
__device__ int   g_cnt[NN];
__device__ int   g_rowptr[NN + 1];
__device__ int   g_cursor[NN + 1];
__device__ int   g_csr[EE];
__device__ int   g_bsums[(NN + SCAN_BLK - 1) / SCAN_BLK + 1];
__device__ float g_stats[128];   // scale[64], shift[64] after reduce

// ---------------------------------------------------------------------------
__device__ __forceinline__ bool edges_are_i64(const void* ei) {
    long long v0 = ((const long long*)ei)[0];
    return (v0 >= 0 && v0 < 1000000LL);
}
__device__ __forceinline__ int edge_at(const void* ei, bool is64, int i) {
    return is64 ? (int)((const long long*)ei)[i] : ((const int*)ei)[i];
}
__device__ __forceinline__ float2 h2f(unsigned u) {
    __half2 h = *reinterpret_cast<__half2*>(&u);
    return __half22float2(h);
}
__device__ __forceinline__ unsigned f2h(float a, float b) {
    __half2 h = __floats2half2_rn(a, b);
    return *reinterpret_cast<unsigned*>(&h);
}

// ---------------------------------------------------------------------------
__global__ void zero_cnt(int* cnt, int n) {
    int i = blockIdx.x * blockDim.x + threadIdx.x;
    if (i < n) cnt[i] = 0;
}

__global__ void hist_dst(const void* ei, int* cnt, int E) {
    int e = blockIdx.x * blockDim.x + threadIdx.x;
    if (e >= E) return;
    bool is64 = edges_are_i64(ei);
    int d = edge_at(ei, is64, E + e);
    atomicAdd(&cnt[d], 1);
}

__global__ void scan1(const int* __restrict__ cnt, int* __restrict__ rowptr,
                      int* __restrict__ bsums, int n) {
    __shared__ int s[SCAN_BLK];
    int t = threadIdx.x;
    int i = blockIdx.x * SCAN_BLK + t;
    int val = (i < n) ? cnt[i] : 0;
    s[t] = val;
    __syncthreads();
    for (int off = 1; off < SCAN_BLK; off <<= 1) {
        int x = (t >= off) ? s[t - off] : 0;
        __syncthreads();
        s[t] += x;
        __syncthreads();
    }
    if (i < n) rowptr[i + 1] = s[t];
    if (t == SCAN_BLK - 1) bsums[blockIdx.x] = s[t];
}

__global__ void scan2(int* bsums, int nb) {
    __shared__ int s[SCAN_BLK];
    int t = threadIdx.x;
    int v = (t < nb) ? bsums[t] : 0;
    s[t] = v;
    __syncthreads();
    for (int off = 1; off < SCAN_BLK; off <<= 1) {
        int x = (t >= off) ? s[t - off] : 0;
        __syncthreads();
        s[t] += x;
        __syncthreads();
    }
    if (t < nb) bsums[t] = s[t] - v;   // exclusive
}

__global__ void scan3(int* __restrict__ rowptr, int* __restrict__ cursor,
                      const int* __restrict__ bsums, const int* __restrict__ cnt,
                      float* __restrict__ dis, int n) {
    int i = blockIdx.x * blockDim.x + threadIdx.x;
    if (i == 0) { rowptr[0] = 0; cursor[0] = 0; }
    if (i < n) {
        int v = rowptr[i + 1] + bsums[i / SCAN_BLK];
        rowptr[i + 1] = v;
        cursor[i + 1] = v;
        dis[i] = rsqrtf((float)(cnt[i] + 1));
    }
}

__global__ void scatter_csr(const void* ei, int* __restrict__ cursor,
                            int* __restrict__ csr, int E) {
    int e = blockIdx.x * blockDim.x + threadIdx.x;
    if (e >= E) return;
    bool is64 = edges_are_i64(ei);
    int s = edge_at(ei, is64, e);
    int d = edge_at(ei, is64, E + e);
    int pos = atomicAdd(&cursor[d], 1);
    csr[pos] = s;
}

// ---------------------------------------------------------------------------
// GEMM: Yh[N,64] = half((X[N,81] @ W[81,64]) * dis[n])
__global__ void gemm81_dis(const float* __restrict__ X, const float* __restrict__ W,
                           const float* __restrict__ dis, __half* __restrict__ Yh, int N) {
    __shared__ float Ws[IND * HID];
    __shared__ float Xs[16][IND];
    int tx = threadIdx.x;
    int ty = threadIdx.y;
    int tid = ty * 64 + tx;
    for (int i = tid; i < IND * HID; i += 256) Ws[i] = W[i];
    int n0 = blockIdx.x * 16;
    for (int i = tid; i < 16 * IND; i += 256) {
        int r = i / IND, c = i % IND;
        int n = n0 + r;
        Xs[r][c] = (n < N) ? X[n * IND + c] : 0.0f;
    }
    __syncthreads();
    float acc[4] = {0.f, 0.f, 0.f, 0.f};
    for (int k = 0; k < IND; ++k) {
        float w = Ws[k * HID + tx];
        #pragma unroll
        for (int r = 0; r < 4; ++r) acc[r] += Xs[ty * 4 + r][k] * w;
    }
    #pragma unroll
    for (int r = 0; r < 4; ++r) {
        int n = n0 + ty * 4 + r;
        if (n < N) Yh[n * HID + tx] = __float2half(acc[r] * __ldg(&dis[n]));
    }
}

// GEMM, fp16 input with fused BN+ReLU: Yh = half((relu(bn(Xh)) @ W) * dis[n])
__global__ void gemm64_bn_dis_h(const __half2* __restrict__ Xh, const float* __restrict__ W,
                                const float* __restrict__ stats, const float* __restrict__ dis,
                                __half* __restrict__ Yh, int N) {
    __shared__ float Ws[HID * HID];
    __shared__ float Xs[16][HID];
    __shared__ float sc[64], sh[64];
    int tx = threadIdx.x;
    int ty = threadIdx.y;
    int tid = ty * 64 + tx;
    for (int i = tid; i < HID * HID; i += 256) Ws[i] = W[i];
    if (tid < 64) { sc[tid] = stats[tid]; sh[tid] = stats[64 + tid]; }
    int n0 = blockIdx.x * 16;
    __syncthreads();
    for (int i = tid; i < 16 * 32; i += 256) {   // 16 rows x 32 half2
        int r = i >> 5, c2 = i & 31;
        int n = n0 + r;
        float2 v = (n < N) ? __half22float2(Xh[n * 32 + c2]) : make_float2(0.f, 0.f);
        int c = 2 * c2;
        Xs[r][c]     = fmaxf(fmaf(v.x, sc[c], sh[c]), 0.0f);
        Xs[r][c + 1] = fmaxf(fmaf(v.y, sc[c + 1], sh[c + 1]), 0.0f);
    }
    __syncthreads();
    float acc[4] = {0.f, 0.f, 0.f, 0.f};
    for (int k = 0; k < HID; ++k) {
        float w = Ws[k * HID + tx];
        #pragma unroll
        for (int r = 0; r < 4; ++r) acc[r] += Xs[ty * 4 + r][k] * w;
    }
    #pragma unroll
    for (int r = 0; r < 4; ++r) {
        int n = n0 + ty * 4 + r;
        if (n < N) Yh[n * HID + tx] = __float2half(acc[r] * __ldg(&dis[n]));
    }
}

// Final heads (fp16 input, fp32 output)
__global__ void gemm_mu_ls_h(const __half2* __restrict__ Xh,
                             const float* __restrict__ Wmu, const float* __restrict__ bmu,
                             const float* __restrict__ Wls, const float* __restrict__ bls,
                             float* __restrict__ out, int N) {
    __shared__ float Ws[HID * 64];
    __shared__ float bs[64];
    __shared__ float Xs[16][HID];
    int tx = threadIdx.x;
    int ty = threadIdx.y;
    int tid = ty * 64 + tx;
    for (int i = tid; i < HID * 64; i += 256) {
        int k = i >> 6, f = i & 63;
        Ws[i] = (f < LAT) ? Wmu[k * LAT + f] : Wls[k * LAT + (f - LAT)];
    }
    if (tid < 64) bs[tid] = (tid < LAT) ? bmu[tid] : bls[tid - LAT];
    int n0 = blockIdx.x * 16;
    for (int i = tid; i < 16 * 32; i += 256) {
        int r = i >> 5, c2 = i & 31;
        int n = n0 + r;
        float2 v = (n < N) ? __half22float2(Xh[n * 32 + c2]) : make_float2(0.f, 0.f);
        Xs[r][2 * c2] = v.x;
        Xs[r][2 * c2 + 1] = v.y;
    }
    __syncthreads();
    float acc[4] = {0.f, 0.f, 0.f, 0.f};
    for (int k = 0; k < HID; ++k) {
        float w = Ws[k * 64 + tx];
        #pragma unroll
        for (int r = 0; r < 4; ++r) acc[r] += Xs[ty * 4 + r][k] * w;
    }
    int f = tx & (LAT - 1);
    long long off = (tx < LAT) ? 0 : (long long)N * LAT;
    #pragma unroll
    for (int r = 0; r < 4; ++r) {
        int n = n0 + ty * 4 + r;
        if (n < N) out[off + (long long)n * LAT + f] = acc[r] + bs[tx];
    }
}

// ---------------------------------------------------------------------------
// Aggregation, 2 nodes per warp (round-5 layout): lanes 0-15 -> node 2w,
// lanes 16-31 -> node 2w+1; each lane loads 8 B (uint2 = 4 feats).
// out[n] = half((sum_{s in nbr(n)} Hs[s] + Hs[n]) * dis[n] + b)   -- fp16 out
__global__ void aggregate_h2(const uint2* __restrict__ Hr, const int* __restrict__ rowptr,
                             const int* __restrict__ csr, const float* __restrict__ dis,
                             const float* __restrict__ bias, uint2* __restrict__ outH, int N) {
    int warp = (blockIdx.x * blockDim.x + threadIdx.x) >> 5;
    int lane = threadIdx.x & 31;
    int grp = lane >> 4;           // 0 or 1
    int sub = lane & 15;           // handles feats 4*sub .. 4*sub+3
    int n = warp * 2 + grp;
    if (n >= N) return;

    uint2 raw = __ldg(&Hr[n * 16 + sub]);
    float2 p0 = h2f(raw.x), p1 = h2f(raw.y);
    float ax0 = p0.x, ay0 = p0.y, az0 = p1.x, aw0 = p1.y;
    float ax1 = 0.f, ay1 = 0.f, az1 = 0.f, aw1 = 0.f;

    int j = __ldg(&rowptr[n]);
    int end = __ldg(&rowptr[n + 1]);
    for (; j + 2 <= end; j += 2) {
        int s0 = __ldg(&csr[j]);
        int s1 = __ldg(&csr[j + 1]);
        uint2 r0 = __ldg(&Hr[s0 * 16 + sub]);
        uint2 r1 = __ldg(&Hr[s1 * 16 + sub]);
        float2 v00 = h2f(r0.x), v01 = h2f(r0.y);
        float2 v10 = h2f(r1.x), v11 = h2f(r1.y);
        ax0 += v00.x; ay0 += v00.y; az0 += v01.x; aw0 += v01.y;
        ax1 += v10.x; ay1 += v10.y; az1 += v11.x; aw1 += v11.y;
    }
    if (j < end) {
        int s0 = __ldg(&csr[j]);
        uint2 r0 = __ldg(&Hr[s0 * 16 + sub]);
        float2 v00 = h2f(r0.x), v01 = h2f(r0.y);
        ax0 += v00.x; ay0 += v00.y; az0 += v01.x; aw0 += v01.y;
    }

    float dd = __ldg(&dis[n]);
    float4 bb = make_float4(0.f, 0.f, 0.f, 0.f);
    if (bias) bb = ((const float4*)bias)[sub];
    uint2 o;
    o.x = f2h(fmaf(ax0 + ax1, dd, bb.x), fmaf(ay0 + ay1, dd, bb.y));
    o.y = f2h(fmaf(az0 + az1, dd, bb.z), fmaf(aw0 + aw1, dd, bb.w));
    outH[n * 16 + sub] = o;
}

// ---------------------------------------------------------------------------
// BN stats on fp16 input: per-block partials, no atomics.
__global__ void bn_stats_h(const __half2* __restrict__ H, float* __restrict__ partial, int N) {
    int tid = threadIdx.x;        // 256
    int c2 = tid & 31;
    int rg = tid >> 5;            // 0..7
    int r = blockIdx.x * 8 + rg;
    int stride = gridDim.x * 8;
    float sx = 0.f, sy = 0.f, qx = 0.f, qy = 0.f;
    for (; r < N; r += stride) {
        float2 v = __half22float2(H[r * 32 + c2]);
        sx += v.x; sy += v.y;
        qx += v.x * v.x; qy += v.y * v.y;
    }
    __shared__ float4 red[256];
    red[tid] = make_float4(sx, sy, qx, qy);
    __syncthreads();
    if (tid < 32) {
        float4 t = red[tid];
        #pragma unroll
        for (int w = 1; w < 8; ++w) {
            float4 u = red[w * 32 + tid];
            t.x += u.x; t.y += u.y; t.z += u.z; t.w += u.w;
        }
        float* p = partial + blockIdx.x * 128;
        p[2 * tid]          = t.x;
        p[2 * tid + 1]      = t.y;
        p[64 + 2 * tid]     = t.z;
        p[64 + 2 * tid + 1] = t.w;
    }
}

// Reduce partials + finalize scale/shift. 128 threads, grid 1.
__global__ void bn_reduce(const float* __restrict__ partial, float* __restrict__ stats,
                          const float* __restrict__ g, const float* __restrict__ beta,
                          int nb, int N) {
    __shared__ float acc[128];
    int tid = threadIdx.x;
    float s = 0.f;
    #pragma unroll 8
    for (int b = 0; b < nb; ++b) s += partial[b * 128 + tid];
    acc[tid] = s;
    __syncthreads();
    if (tid < 64) {
        float invN = 1.0f / (float)N;
        float m = acc[tid] * invN;
        float v = acc[64 + tid] * invN - m * m;
        float scale = g[tid] * rsqrtf(v + BN_EPS);
        stats[tid] = scale;
        stats[64 + tid] = beta[tid] - m * scale;
    }
}

// Hs[n] = half(relu(bn(in[n])) * dis[n]) ; fp16 -> fp16
__global__ void bn_relu_dis_h(const __half2* __restrict__ H, const float* __restrict__ stats,
                              const float* __restrict__ dis, __half2* __restrict__ out, int total2) {
    int idx = blockIdx.x * blockDim.x + threadIdx.x;
    if (idx >= total2) return;
    int c2 = idx & 31;
    int n = idx >> 5;
    float2 v = __half22float2(H[idx]);
    int c = 2 * c2;
    float dd = __ldg(&dis[n]);
    float yx = fmaxf(fmaf(v.x, __ldg(&stats[c]), __ldg(&stats[64 + c])), 0.0f) * dd;
    float yy = fmaxf(fmaf(v.y, __ldg(&stats[c + 1]), __ldg(&stats[64 + c + 1])), 0.0f) * dd;
    out[idx] = __floats2half2_rn(yx, yy);
}

// ---------------------------------------------------------------------------
extern "C" void kernel_launch(void* const* d_in, const int* in_sizes, int n_in,
                              void* d_out, int out_size) {
    const float* x    = (const float*)d_in[0];
    const void*  ei   = d_in[1];
    const float* W1   = (const float*)d_in[2];
    const float* b1   = (const float*)d_in[3];
    const float* g1   = (const float*)d_in[4];
    const float* be1  = (const float*)d_in[5];
    const float* W2   = (const float*)d_in[6];
    const float* b2   = (const float*)d_in[7];
    const float* g2   = (const float*)d_in[8];
    const float* be2  = (const float*)d_in[9];
    const float* Wmu  = (const float*)d_in[10];
    const float* bmu  = (const float*)d_in[11];
    const float* Wls  = (const float*)d_in[12];
    const float* bls  = (const float*)d_in[13];
    float* out = (float*)d_out;

    int N = in_sizes[0] / IND;
    int E = in_sizes[1] / 2;

    float *pA, *pB, *pDis, *pStats;
    __half2* pH;
    int *pCnt, *pRow, *pCur, *pCsr, *pBs;
    cudaGetSymbolAddress((void**)&pA, g_bufA);
    cudaGetSymbolAddress((void**)&pB, g_bufB);
    cudaGetSymbolAddress((void**)&pDis, g_dis);
    cudaGetSymbolAddress((void**)&pStats, g_stats);
    cudaGetSymbolAddress((void**)&pH, g_half);
    cudaGetSymbolAddress((void**)&pCnt, g_cnt);
    cudaGetSymbolAddress((void**)&pRow, g_rowptr);
    cudaGetSymbolAddress((void**)&pCur, g_cursor);
    cudaGetSymbolAddress((void**)&pCsr, g_csr);
    cudaGetSymbolAddress((void**)&pBs, g_bsums);

    __half2* pGh = (__half2*)pA;     // fp16 aggregate output
    float* pPart = pB;               // BN partials (512*128 floats)

    int nScanBlocks = (N + SCAN_BLK - 1) / SCAN_BLK;
    dim3 gThr(64, 4);
    int gemmGrid = (N + 15) / 16;
    int aggGrid = ((N + 1) / 2 * 32 + 255) / 256;   // 2 nodes/warp, 8 warps/block
    int total2 = N * 32;

    // 1. CSR build + normalization
    zero_cnt<<<(N + 255) / 256, 256>>>(pCnt, N);
    hist_dst<<<(E + 255) / 256, 256>>>(ei, pCnt, E);
    scan1<<<nScanBlocks, SCAN_BLK>>>(pCnt, pRow, pBs, N);
    scan2<<<1, SCAN_BLK>>>(pBs, nScanBlocks);
    scan3<<<(N + 255) / 256, 256>>>(pRow, pCur, pBs, pCnt, pDis, N);
    scatter_csr<<<(E + 255) / 256, 256>>>(ei, pCur, pCsr, E);

    // 2. conv1
    gemm81_dis<<<gemmGrid, gThr>>>(x, W1, pDis, (__half*)pH, N);
    aggregate_h2<<<aggGrid, 256>>>((const uint2*)pH, pRow, pCsr, pDis, b1, (uint2*)pGh, N);

    // 3. BN1 stats (two-stage, no atomics)
    bn_stats_h<<<STATS_BLOCKS, 256>>>(pGh, pPart, N);
    bn_reduce<<<1, 128>>>(pPart, pStats, g1, be1, STATS_BLOCKS, N);

    // 4. conv2 (BN1 apply + ReLU fused into GEMM input)
    gemm64_bn_dis_h<<<gemmGrid, gThr>>>(pGh, W2, pStats, pDis, (__half*)pH, N);
    aggregate_h2<<<aggGrid, 256>>>((const uint2*)pH, pRow, pCsr, pDis, b2, (uint2*)pGh, N);

    // 5. BN2 stats
    bn_stats_h<<<STATS_BLOCKS, 256>>>(pGh, pPart, N);
    bn_reduce<<<1, 128>>>(pPart, pStats, g2, be2, STATS_BLOCKS, N);

    // 6. Hs = relu(bn(.)) * dis ; shared aggregation for both heads
    bn_relu_dis_h<<<(total2 + 255) / 256, 256>>>(pGh, pStats, pDis, pH, total2);
    aggregate_h2<<<aggGrid, 256>>>((const uint2*)pH, pRow, pCsr, pDis, (const float*)nullptr,
                                   (uint2*)pGh, N);

    // 7. heads
    gemm_mu_ls_h<<<gemmGrid, gThr>>>(pGh, Wmu, bmu, Wls, bls, out, N);
}

// round 8
// speedup vs baseline: 1.0470x; 1.0373x over previous
#include <cuda_runtime.h>
#include <cuda_fp16.h>
#include <cuda_bf16.h>

#define NN 100000
#define EE 3200000
#define IND 81
#define INDP 84   // padded row length (16B-aligned float4 rows)
#define HID 64
#define LAT 32
#define BN_EPS 1e-5f
#define SCAN_BLK 1024

// Scratch (device globals; no allocation allowed)
__device__ __align__(128) __half2 g_half[NN * 32];   // fp16 Hs rows (64 feats = 32 half2)
__device__ float g_bufA[NN * HID];
__device__ float g_bufB[NN * HID];
__device__ float g_dis[NN];
__device__ int   g_cnt[NN];
__device__ int   g_rowptr[NN + 1];
__device__ int   g_cursor[NN + 1];
__device__ int   g_csr[EE];
__device__ int   g_bsums[(NN + SCAN_BLK - 1) / SCAN_BLK + 1];
__device__ float g_stats[128];   // sum[64], sumsq[64] -> scale[64], shift[64]

// ---------------------------------------------------------------------------
__device__ __forceinline__ bool edges_are_i64(const void* ei) {
    long long v0 = ((const long long*)ei)[0];
    return (v0 >= 0 && v0 < 1000000LL);
}
__device__ __forceinline__ int edge_at(const void* ei, bool is64, int i) {
    return is64 ? (int)((const long long*)ei)[i] : ((const int*)ei)[i];
}

// ---------------------------------------------------------------------------
__global__ void zero_cnt(int* cnt, int n) {
    int i = blockIdx.x * blockDim.x + threadIdx.x;
    if (i < n) cnt[i] = 0;
}

__global__ void hist_dst(const void* ei, int* cnt, int E) {
    int e = blockIdx.x * blockDim.x + threadIdx.x;
    if (e >= E) return;
    bool is64 = edges_are_i64(ei);
    int d = edge_at(ei, is64, E + e);
    atomicAdd(&cnt[d], 1);
}

__global__ void scan1(const int* __restrict__ cnt, int* __restrict__ rowptr,
                      int* __restrict__ bsums, int n) {
    __shared__ int s[SCAN_BLK];
    int t = threadIdx.x;
    int i = blockIdx.x * SCAN_BLK + t;
    int val = (i < n) ? cnt[i] : 0;
    s[t] = val;
    __syncthreads();
    for (int off = 1; off < SCAN_BLK; off <<= 1) {
        int x = (t >= off) ? s[t - off] : 0;
        __syncthreads();
        s[t] += x;
        __syncthreads();
    }
    if (i < n) rowptr[i + 1] = s[t];
    if (t == SCAN_BLK - 1) bsums[blockIdx.x] = s[t];
}

__global__ void scan2(int* bsums, int nb) {
    __shared__ int s[SCAN_BLK];
    int t = threadIdx.x;
    int v = (t < nb) ? bsums[t] : 0;
    s[t] = v;
    __syncthreads();
    for (int off = 1; off < SCAN_BLK; off <<= 1) {
        int x = (t >= off) ? s[t - off] : 0;
        __syncthreads();
        s[t] += x;
        __syncthreads();
    }
    if (t < nb) bsums[t] = s[t] - v;   // exclusive
}

__global__ void scan3(int* __restrict__ rowptr, int* __restrict__ cursor,
                      const int* __restrict__ bsums, const int* __restrict__ cnt,
                      float* __restrict__ dis, int n) {
    int i = blockIdx.x * blockDim.x + threadIdx.x;
    if (i == 0) { rowptr[0] = 0; cursor[0] = 0; }
    if (i < n) {
        int v = rowptr[i + 1] + bsums[i / SCAN_BLK];
        rowptr[i + 1] = v;
        cursor[i + 1] = v;
        dis[i] = rsqrtf((float)(cnt[i] + 1));
    }
}

__global__ void scatter_csr(const void* ei, int* __restrict__ cursor,
                            int* __restrict__ csr, int E) {
    int e = blockIdx.x * blockDim.x + threadIdx.x;
    if (e >= E) return;
    bool is64 = edges_are_i64(ei);
    int s = edge_at(ei, is64, e);
    int d = edge_at(ei, is64, E + e);
    int pos = atomicAdd(&cursor[d], 1);
    csr[pos] = s;
}

// ---------------------------------------------------------------------------
// GEMM: Yh[N,64] = half((X[N,81] @ W[81,64]) * dis[n])
// k-unroll-4 with float4 broadcast LDS on Xs (padded rows for alignment).
__global__ void gemm81_dis(const float* __restrict__ X, const float* __restrict__ W,
                           const float* __restrict__ dis, __half* __restrict__ Yh, int N) {
    __shared__ float Ws[IND * HID];
    __shared__ __align__(16) float Xs[16][INDP];
    int tx = threadIdx.x;
    int ty = threadIdx.y;
    int tid = ty * 64 + tx;
    for (int i = tid; i < IND * HID; i += 256) Ws[i] = W[i];
    int n0 = blockIdx.x * 16;
    for (int i = tid; i < 16 * IND; i += 256) {
        int r = i / IND, c = i % IND;
        int n = n0 + r;
        Xs[r][c] = (n < N) ? X[n * IND + c] : 0.0f;
    }
    __syncthreads();
    float acc[4] = {0.f, 0.f, 0.f, 0.f};
    #pragma unroll 5
    for (int k = 0; k < 80; k += 4) {
        float w0 = Ws[(k + 0) * HID + tx];
        float w1 = Ws[(k + 1) * HID + tx];
        float w2 = Ws[(k + 2) * HID + tx];
        float w3 = Ws[(k + 3) * HID + tx];
        #pragma unroll
        for (int r = 0; r < 4; ++r) {
            float4 xv = *reinterpret_cast<const float4*>(&Xs[ty * 4 + r][k]);
            acc[r] += xv.x * w0 + xv.y * w1 + xv.z * w2 + xv.w * w3;
        }
    }
    {   // k = 80 remainder
        float w = Ws[80 * HID + tx];
        #pragma unroll
        for (int r = 0; r < 4; ++r) acc[r] += Xs[ty * 4 + r][80] * w;
    }
    #pragma unroll
    for (int r = 0; r < 4; ++r) {
        int n = n0 + ty * 4 + r;
        if (n < N) Yh[n * HID + tx] = __float2half(acc[r] * __ldg(&dis[n]));
    }
}

// GEMM with fused BN+ReLU input: Yh = half((relu(bn(X)) @ W) * dis[n])
__global__ void gemm64_bn_dis(const float* __restrict__ X, const float* __restrict__ W,
                              const float* __restrict__ stats, const float* __restrict__ dis,
                              __half* __restrict__ Yh, int N) {
    __shared__ float Ws[HID * HID];
    __shared__ __align__(16) float Xs[16][HID];
    __shared__ float sc[64], sh[64];
    int tx = threadIdx.x;
    int ty = threadIdx.y;
    int tid = ty * 64 + tx;
    for (int i = tid; i < HID * HID; i += 256) Ws[i] = W[i];
    if (tid < 64) { sc[tid] = stats[tid]; sh[tid] = stats[64 + tid]; }
    int n0 = blockIdx.x * 16;
    __syncthreads();
    for (int i = tid; i < 16 * HID; i += 256) {
        int r = i >> 6, c = i & 63;
        int n = n0 + r;
        float raw = (n < N) ? X[n * HID + c] : 0.0f;
        Xs[r][c] = fmaxf(fmaf(raw, sc[c], sh[c]), 0.0f);
    }
    __syncthreads();
    float acc[4] = {0.f, 0.f, 0.f, 0.f};
    #pragma unroll 4
    for (int k = 0; k < HID; k += 4) {
        float w0 = Ws[(k + 0) * HID + tx];
        float w1 = Ws[(k + 1) * HID + tx];
        float w2 = Ws[(k + 2) * HID + tx];
        float w3 = Ws[(k + 3) * HID + tx];
        #pragma unroll
        for (int r = 0; r < 4; ++r) {
            float4 xv = *reinterpret_cast<const float4*>(&Xs[ty * 4 + r][k]);
            acc[r] += xv.x * w0 + xv.y * w1 + xv.z * w2 + xv.w * w3;
        }
    }
    #pragma unroll
    for (int r = 0; r < 4; ++r) {
        int n = n0 + ty * 4 + r;
        if (n < N) Yh[n * HID + tx] = __float2half(acc[r] * __ldg(&dis[n]));
    }
}

// Final heads
__global__ void gemm_mu_ls(const float* __restrict__ X,
                           const float* __restrict__ Wmu, const float* __restrict__ bmu,
                           const float* __restrict__ Wls, const float* __restrict__ bls,
                           float* __restrict__ out, int N) {
    __shared__ float Ws[HID * 64];
    __shared__ float bs[64];
    __shared__ __align__(16) float Xs[16][HID];
    int tx = threadIdx.x;
    int ty = threadIdx.y;
    int tid = ty * 64 + tx;
    for (int i = tid; i < HID * 64; i += 256) {
        int k = i >> 6, f = i & 63;
        Ws[i] = (f < LAT) ? Wmu[k * LAT + f] : Wls[k * LAT + (f - LAT)];
    }
    if (tid < 64) bs[tid] = (tid < LAT) ? bmu[tid] : bls[tid - LAT];
    int n0 = blockIdx.x * 16;
    for (int i = tid; i < 16 * HID; i += 256) {
        int r = i >> 6, c = i & 63;
        int n = n0 + r;
        Xs[r][c] = (n < N) ? X[n * HID + c] : 0.0f;
    }
    __syncthreads();
    float acc[4] = {0.f, 0.f, 0.f, 0.f};
    #pragma unroll 4
    for (int k = 0; k < HID; k += 4) {
        float w0 = Ws[(k + 0) * 64 + tx];
        float w1 = Ws[(k + 1) * 64 + tx];
        float w2 = Ws[(k + 2) * 64 + tx];
        float w3 = Ws[(k + 3) * 64 + tx];
        #pragma unroll
        for (int r = 0; r < 4; ++r) {
            float4 xv = *reinterpret_cast<const float4*>(&Xs[ty * 4 + r][k]);
            acc[r] += xv.x * w0 + xv.y * w1 + xv.z * w2 + xv.w * w3;
        }
    }
    int f = tx & (LAT - 1);
    long long off = (tx < LAT) ? 0 : (long long)N * LAT;
    #pragma unroll
    for (int r = 0; r < 4; ++r) {
        int n = n0 + ty * 4 + r;
        if (n < N) out[off + (long long)n * LAT + f] = acc[r] + bs[tx];
    }
}

// ---------------------------------------------------------------------------
// Aggregation, 2 nodes per warp: lanes 0-15 -> node 2w, lanes 16-31 -> node 2w+1.
// Each lane loads 8 B (uint2 = 2 half2 = 4 feats); one warp LDG covers 2 rows.
// out[n] = (sum_{s in nbr(n)} Hs[s] + Hs[n]) * dis[n] + b   (fp32 out)
__global__ void aggregate_h2(const __half2* __restrict__ Hh, const int* __restrict__ rowptr,
                             const int* __restrict__ csr, const float* __restrict__ dis,
                             const float* __restrict__ bias, float4* __restrict__ out4, int N) {
    int warp = (blockIdx.x * blockDim.x + threadIdx.x) >> 5;
    int lane = threadIdx.x & 31;
    int grp = lane >> 4;           // 0 or 1
    int sub = lane & 15;           // 0..15: handles feats 4*sub..4*sub+3
    int n = warp * 2 + grp;
    if (n >= N) return;

    const uint2* Hr = (const uint2*)Hh;   // 16 uint2 per row
    uint2 raw = __ldg(&Hr[n * 16 + sub]);
    __half2 h0 = *reinterpret_cast<__half2*>(&raw.x);
    __half2 h1 = *reinterpret_cast<__half2*>(&raw.y);
    float2 p0 = __half22float2(h0), p1 = __half22float2(h1);
    float ax0 = p0.x, ay0 = p0.y, az0 = p1.x, aw0 = p1.y;
    float ax1 = 0.f, ay1 = 0.f, az1 = 0.f, aw1 = 0.f;

    int j = __ldg(&rowptr[n]);
    int end = __ldg(&rowptr[n + 1]);
    for (; j + 2 <= end; j += 2) {
        int s0 = __ldg(&csr[j]);
        int s1 = __ldg(&csr[j + 1]);
        uint2 r0 = __ldg(&Hr[s0 * 16 + sub]);
        uint2 r1 = __ldg(&Hr[s1 * 16 + sub]);
        float2 v00 = __half22float2(*reinterpret_cast<__half2*>(&r0.x));
        float2 v01 = __half22float2(*reinterpret_cast<__half2*>(&r0.y));
        float2 v10 = __half22float2(*reinterpret_cast<__half2*>(&r1.x));
        float2 v11 = __half22float2(*reinterpret_cast<__half2*>(&r1.y));
        ax0 += v00.x; ay0 += v00.y; az0 += v01.x; aw0 += v01.y;
        ax1 += v10.x; ay1 += v10.y; az1 += v11.x; aw1 += v11.y;
    }
    if (j < end) {
        int s0 = __ldg(&csr[j]);
        uint2 r0 = __ldg(&Hr[s0 * 16 + sub]);
        float2 v00 = __half22float2(*reinterpret_cast<__half2*>(&r0.x));
        float2 v01 = __half22float2(*reinterpret_cast<__half2*>(&r0.y));
        ax0 += v00.x; ay0 += v00.y; az0 += v01.x; aw0 += v01.y;
    }

    float dd = __ldg(&dis[n]);
    float4 bb = make_float4(0.f, 0.f, 0.f, 0.f);
    if (bias) bb = ((const float4*)bias)[sub];
    out4[n * 16 + sub] = make_float4(fmaf(ax0 + ax1, dd, bb.x),
                                     fmaf(ay0 + ay1, dd, bb.y),
                                     fmaf(az0 + az1, dd, bb.z),
                                     fmaf(aw0 + aw1, dd, bb.w));
}

// ---------------------------------------------------------------------------
// BatchNorm (separate full-pass stats — round-5 structure)
__global__ void zero_stats(float* stats) {
    int i = threadIdx.x;
    if (i < 128) stats[i] = 0.0f;
}

__global__ void bn_stats(const float* __restrict__ H, float* stats, int N) {
    int tid = threadIdx.x;
    int col = tid & 63;
    int r = blockIdx.x * 4 + (tid >> 6);
    int rstride = gridDim.x * 4;
    float s = 0.0f, q = 0.0f;
    for (; r < N; r += rstride) {
        float v = H[r * HID + col];
        s += v; q += v * v;
    }
    __shared__ float sh[256], qh[256];
    sh[tid] = s; qh[tid] = q;
    __syncthreads();
    if (tid < 64) {
        float S = sh[tid] + sh[tid + 64] + sh[tid + 128] + sh[tid + 192];
        float Q = qh[tid] + qh[tid + 64] + qh[tid + 128] + qh[tid + 192];
        atomicAdd(&stats[tid], S);
        atomicAdd(&stats[64 + tid], Q);
    }
}

__global__ void bn_finalize(float* stats, const float* __restrict__ g,
                            const float* __restrict__ beta, int N) {
    int f = threadIdx.x;
    if (f >= 64) return;
    float invN = 1.0f / (float)N;
    float m = stats[f] * invN;
    float v = stats[64 + f] * invN - m * m;
    float scale = g[f] * rsqrtf(v + BN_EPS);
    stats[f] = scale;
    stats[64 + f] = beta[f] - m * scale;
}

// Hs[n,f] = half(relu(bn(B[n,f])) * dis[n])
__global__ void bn_relu_dis(const float* __restrict__ H, const float* __restrict__ stats,
                            const float* __restrict__ dis, __half* __restrict__ out, int total) {
    int idx = blockIdx.x * blockDim.x + threadIdx.x;
    if (idx >= total) return;
    int f = idx & 63;
    int n = idx >> 6;
    float y = fmaxf(fmaf(H[idx], stats[f], stats[64 + f]), 0.0f);
    out[idx] = __float2half(y * __ldg(&dis[n]));
}

// ---------------------------------------------------------------------------
extern "C" void kernel_launch(void* const* d_in, const int* in_sizes, int n_in,
                              void* d_out, int out_size) {
    const float* x    = (const float*)d_in[0];
    const void*  ei   = d_in[1];
    const float* W1   = (const float*)d_in[2];
    const float* b1   = (const float*)d_in[3];
    const float* g1   = (const float*)d_in[4];
    const float* be1  = (const float*)d_in[5];
    const float* W2   = (const float*)d_in[6];
    const float* b2   = (const float*)d_in[7];
    const float* g2   = (const float*)d_in[8];
    const float* be2  = (const float*)d_in[9];
    const float* Wmu  = (const float*)d_in[10];
    const float* bmu  = (const float*)d_in[11];
    const float* Wls  = (const float*)d_in[12];
    const float* bls  = (const float*)d_in[13];
    float* out = (float*)d_out;

    int N = in_sizes[0] / IND;
    int E = in_sizes[1] / 2;

    float *pA, *pB, *pDis, *pStats;
    __half2* pH;
    int *pCnt, *pRow, *pCur, *pCsr, *pBs;
    cudaGetSymbolAddress((void**)&pA, g_bufA);
    cudaGetSymbolAddress((void**)&pB, g_bufB);
    cudaGetSymbolAddress((void**)&pDis, g_dis);
    cudaGetSymbolAddress((void**)&pStats, g_stats);
    cudaGetSymbolAddress((void**)&pH, g_half);
    cudaGetSymbolAddress((void**)&pCnt, g_cnt);
    cudaGetSymbolAddress((void**)&pRow, g_rowptr);
    cudaGetSymbolAddress((void**)&pCur, g_cursor);
    cudaGetSymbolAddress((void**)&pCsr, g_csr);
    cudaGetSymbolAddress((void**)&pBs, g_bsums);

    int NH = N * HID;
    int nScanBlocks = (N + SCAN_BLK - 1) / SCAN_BLK;
    dim3 gThr(64, 4);
    int gemmGrid = (N + 15) / 16;
    int aggGrid = ((N + 1) / 2 * 32 + 255) / 256;   // 2 nodes per warp, 8 warps/block

    // 1. CSR build + normalization
    zero_cnt<<<(N + 255) / 256, 256>>>(pCnt, N);
    hist_dst<<<(E + 255) / 256, 256>>>(ei, pCnt, E);
    scan1<<<nScanBlocks, SCAN_BLK>>>(pCnt, pRow, pBs, N);
    scan2<<<1, SCAN_BLK>>>(pBs, nScanBlocks);
    scan3<<<(N + 255) / 256, 256>>>(pRow, pCur, pBs, pCnt, pDis, N);
    scatter_csr<<<(E + 255) / 256, 256>>>(ei, pCur, pCsr, E);

    // 2. conv1
    gemm81_dis<<<gemmGrid, gThr>>>(x, W1, pDis, (__half*)pH, N);
    aggregate_h2<<<aggGrid, 256>>>(pH, pRow, pCsr, pDis, b1, (float4*)pB, N);

    // 3. BN1 stats
    zero_stats<<<1, 128>>>(pStats);
    bn_stats<<<512, 256>>>(pB, pStats, N);
    bn_finalize<<<1, 64>>>(pStats, g1, be1, N);

    // 4. conv2 (BN1 apply fused into GEMM input)
    gemm64_bn_dis<<<gemmGrid, gThr>>>(pB, W2, pStats, pDis, (__half*)pH, N);
    aggregate_h2<<<aggGrid, 256>>>(pH, pRow, pCsr, pDis, b2, (float4*)pA, N);

    // 5. BN2 stats
    zero_stats<<<1, 128>>>(pStats);
    bn_stats<<<512, 256>>>(pA, pStats, N);
    bn_finalize<<<1, 64>>>(pStats, g2, be2, N);

    // 6. Hs = relu(bn(A)) * dis ; shared aggregation for both heads
    bn_relu_dis<<<(NH + 255) / 256, 256>>>(pA, pStats, pDis, (__half*)pH, NH);
    aggregate_h2<<<aggGrid, 256>>>(pH, pRow, pCsr, pDis, (const float*)nullptr, (float4*)pB, N);

    // 7. heads
    gemm_mu_ls<<<gemmGrid, gThr>>>(pB, Wmu, bmu, Wls, bls, out, N);
}

// round 9
// speedup vs baseline: 1.0593x; 1.0117x over previous
#include <cuda_runtime.h>
#include <cuda_fp16.h>
#include <cuda_bf16.h>

#define NN 100000
#define EE 3200000
#define IND 81
#define INDP 84
#define HID 64
#define LAT 32
#define BN_EPS 1e-5f
#define SCAN_BLK 1024

// Scratch (device globals; no allocation allowed)
__device__ __align__(128) __half2 g_half[NN * 32];   // fp16 Hs rows
__device__ float g_bufA[NN * HID];
__device__ float g_bufB[NN * HID];
__device__ float g_dis[NN];
__device__ int   g_cnt[NN];
__device__ int   g_rowptr[NN + 1];
__device__ int   g_cursor[NN + 1];
__device__ int   g_csr[EE];
__device__ int   g_bsums[(NN + SCAN_BLK - 1) / SCAN_BLK + 1];
__device__ float g_stats[256];   // [0:128) BN1 raw sums, [128:256) BN2 raw sums

// ---------------------------------------------------------------------------
__device__ __forceinline__ bool edges_are_i64(const void* ei) {
    long long v0 = ((const long long*)ei)[0];
    return (v0 >= 0 && v0 < 1000000LL);
}
__device__ __forceinline__ int edge_at(const void* ei, bool is64, int i) {
    return is64 ? (int)((const long long*)ei)[i] : ((const int*)ei)[i];
}

// ---------------------------------------------------------------------------
__global__ void hist_dst(const void* ei, int* cnt, int E) {
    int e = blockIdx.x * blockDim.x + threadIdx.x;
    if (e >= E) return;
    bool is64 = edges_are_i64(ei);
    int d = edge_at(ei, is64, E + e);
    atomicAdd(&cnt[d], 1);
}

// per-block inclusive scan of cnt -> rowptr[i+1] (block-local), raw block sums -> bsums
__global__ void scan1(const int* __restrict__ cnt, int* __restrict__ rowptr,
                      int* __restrict__ bsums, int n) {
    __shared__ int s[SCAN_BLK];
    int t = threadIdx.x;
    int i = blockIdx.x * SCAN_BLK + t;
    int val = (i < n) ? cnt[i] : 0;
    s[t] = val;
    __syncthreads();
    for (int off = 1; off < SCAN_BLK; off <<= 1) {
        int x = (t >= off) ? s[t - off] : 0;
        __syncthreads();
        s[t] += x;
        __syncthreads();
    }
    if (i < n) rowptr[i + 1] = s[t];
    if (t == SCAN_BLK - 1) bsums[blockIdx.x] = s[t];
}

// Add bsums prefix (computed inline per block), init cursor, dis = rsqrt(deg+1).
// Each 256-thread block covers i in [base, base+256): at most 2 distinct scan-block
// indices. Two warps each compute one needed exclusive prefix over raw bsums.
__global__ void scan3(int* __restrict__ rowptr, int* __restrict__ cursor,
                      const int* __restrict__ bsums, const int* __restrict__ cnt,
                      float* __restrict__ dis, int n, int nb) {
    __shared__ int pre[2];
    int t = threadIdx.x;
    int base = blockIdx.x * 256;
    int jmin = base / SCAN_BLK;
    int jmax = (base + 255) / SCAN_BLK;
    int wid = t >> 5, lane = t & 31;
    if (wid < 2) {
        int j = (wid == 0) ? jmin : jmax;   // exclusive prefix over bsums[0..j)
        int s = 0;
        for (int k = lane; k < j; k += 32) s += bsums[k];
        #pragma unroll
        for (int o = 16; o > 0; o >>= 1) s += __shfl_down_sync(0xffffffffu, s, o);
        if (lane == 0) pre[wid] = s;
    }
    __syncthreads();
    int i = base + t;
    if (i == 0) { rowptr[0] = 0; cursor[0] = 0; }
    if (i < n) {
        int myj = i / SCAN_BLK;
        int off = (myj == jmin) ? pre[0] : pre[1];
        int v = rowptr[i + 1] + off;
        rowptr[i + 1] = v;
        cursor[i + 1] = v;
        dis[i] = rsqrtf((float)(cnt[i] + 1));
    }
}

__global__ void scatter_csr(const void* ei, int* __restrict__ cursor,
                            int* __restrict__ csr, int E) {
    int e = blockIdx.x * blockDim.x + threadIdx.x;
    if (e >= E) return;
    bool is64 = edges_are_i64(ei);
    int s = edge_at(ei, is64, e);
    int d = edge_at(ei, is64, E + e);
    int pos = atomicAdd(&cursor[d], 1);
    csr[pos] = s;
}

// ---------------------------------------------------------------------------
// GEMM: Yh[N,64] = half((X[N,81] @ W[81,64]) * dis[n])
__global__ void gemm81_dis(const float* __restrict__ X, const float* __restrict__ W,
                           const float* __restrict__ dis, __half* __restrict__ Yh, int N) {
    __shared__ float Ws[IND * HID];
    __shared__ __align__(16) float Xs[16][INDP];
    int tx = threadIdx.x;
    int ty = threadIdx.y;
    int tid = ty * 64 + tx;
    for (int i = tid; i < IND * HID; i += 256) Ws[i] = W[i];
    int n0 = blockIdx.x * 16;
    for (int i = tid; i < 16 * IND; i += 256) {
        int r = i / IND, c = i % IND;
        int n = n0 + r;
        Xs[r][c] = (n < N) ? X[n * IND + c] : 0.0f;
    }
    __syncthreads();
    float acc[4] = {0.f, 0.f, 0.f, 0.f};
    #pragma unroll 5
    for (int k = 0; k < 80; k += 4) {
        float w0 = Ws[(k + 0) * HID + tx];
        float w1 = Ws[(k + 1) * HID + tx];
        float w2 = Ws[(k + 2) * HID + tx];
        float w3 = Ws[(k + 3) * HID + tx];
        #pragma unroll
        for (int r = 0; r < 4; ++r) {
            float4 xv = *reinterpret_cast<const float4*>(&Xs[ty * 4 + r][k]);
            acc[r] += xv.x * w0 + xv.y * w1 + xv.z * w2 + xv.w * w3;
        }
    }
    {
        float w = Ws[80 * HID + tx];
        #pragma unroll
        for (int r = 0; r < 4; ++r) acc[r] += Xs[ty * 4 + r][80] * w;
    }
    #pragma unroll
    for (int r = 0; r < 4; ++r) {
        int n = n0 + ty * 4 + r;
        if (n < N) Yh[n * HID + tx] = __float2half(acc[r] * __ldg(&dis[n]));
    }
}

// GEMM with fused BN-finalize + BN-apply + ReLU input transform.
// rawstats: sum[64], sumsq[64]. Yh = half((relu(bn(X)) @ W) * dis[n])
__global__ void gemm64_bn_dis(const float* __restrict__ X, const float* __restrict__ W,
                              const float* __restrict__ rawstats,
                              const float* __restrict__ g, const float* __restrict__ beta,
                              const float* __restrict__ dis,
                              __half* __restrict__ Yh, int N) {
    __shared__ float Ws[HID * HID];
    __shared__ __align__(16) float Xs[16][HID];
    __shared__ float sc[64], sh[64];
    int tx = threadIdx.x;
    int ty = threadIdx.y;
    int tid = ty * 64 + tx;
    for (int i = tid; i < HID * HID; i += 256) Ws[i] = W[i];
    if (tid < 64) {
        float invN = 1.0f / (float)N;
        float m = rawstats[tid] * invN;
        float v = rawstats[64 + tid] * invN - m * m;
        float scale = g[tid] * rsqrtf(v + BN_EPS);
        sc[tid] = scale;
        sh[tid] = beta[tid] - m * scale;
    }
    int n0 = blockIdx.x * 16;
    __syncthreads();
    for (int i = tid; i < 16 * HID; i += 256) {
        int r = i >> 6, c = i & 63;
        int n = n0 + r;
        float raw = (n < N) ? X[n * HID + c] : 0.0f;
        Xs[r][c] = fmaxf(fmaf(raw, sc[c], sh[c]), 0.0f);
    }
    __syncthreads();
    float acc[4] = {0.f, 0.f, 0.f, 0.f};
    #pragma unroll 4
    for (int k = 0; k < HID; k += 4) {
        float w0 = Ws[(k + 0) * HID + tx];
        float w1 = Ws[(k + 1) * HID + tx];
        float w2 = Ws[(k + 2) * HID + tx];
        float w3 = Ws[(k + 3) * HID + tx];
        #pragma unroll
        for (int r = 0; r < 4; ++r) {
            float4 xv = *reinterpret_cast<const float4*>(&Xs[ty * 4 + r][k]);
            acc[r] += xv.x * w0 + xv.y * w1 + xv.z * w2 + xv.w * w3;
        }
    }
    #pragma unroll
    for (int r = 0; r < 4; ++r) {
        int n = n0 + ty * 4 + r;
        if (n < N) Yh[n * HID + tx] = __float2half(acc[r] * __ldg(&dis[n]));
    }
}

// Final heads
__global__ void gemm_mu_ls(const float* __restrict__ X,
                           const float* __restrict__ Wmu, const float* __restrict__ bmu,
                           const float* __restrict__ Wls, const float* __restrict__ bls,
                           float* __restrict__ out, int N) {
    __shared__ float Ws[HID * 64];
    __shared__ float bs[64];
    __shared__ __align__(16) float Xs[16][HID];
    int tx = threadIdx.x;
    int ty = threadIdx.y;
    int tid = ty * 64 + tx;
    for (int i = tid; i < HID * 64; i += 256) {
        int k = i >> 6, f = i & 63;
        Ws[i] = (f < LAT) ? Wmu[k * LAT + f] : Wls[k * LAT + (f - LAT)];
    }
    if (tid < 64) bs[tid] = (tid < LAT) ? bmu[tid] : bls[tid - LAT];
    int n0 = blockIdx.x * 16;
    for (int i = tid; i < 16 * HID; i += 256) {
        int r = i >> 6, c = i & 63;
        int n = n0 + r;
        Xs[r][c] = (n < N) ? X[n * HID + c] : 0.0f;
    }
    __syncthreads();
    float acc[4] = {0.f, 0.f, 0.f, 0.f};
    #pragma unroll 4
    for (int k = 0; k < HID; k += 4) {
        float w0 = Ws[(k + 0) * 64 + tx];
        float w1 = Ws[(k + 1) * 64 + tx];
        float w2 = Ws[(k + 2) * 64 + tx];
        float w3 = Ws[(k + 3) * 64 + tx];
        #pragma unroll
        for (int r = 0; r < 4; ++r) {
            float4 xv = *reinterpret_cast<const float4*>(&Xs[ty * 4 + r][k]);
            acc[r] += xv.x * w0 + xv.y * w1 + xv.z * w2 + xv.w * w3;
        }
    }
    int f = tx & (LAT - 1);
    long long off = (tx < LAT) ? 0 : (long long)N * LAT;
    #pragma unroll
    for (int r = 0; r < 4; ++r) {
        int n = n0 + ty * 4 + r;
        if (n < N) out[off + (long long)n * LAT + f] = acc[r] + bs[tx];
    }
}

// ---------------------------------------------------------------------------
// Aggregation, 2 nodes per warp (unchanged from 391.7us version)
__global__ void aggregate_h2(const __half2* __restrict__ Hh, const int* __restrict__ rowptr,
                             const int* __restrict__ csr, const float* __restrict__ dis,
                             const float* __restrict__ bias, float4* __restrict__ out4, int N) {
    int warp = (blockIdx.x * blockDim.x + threadIdx.x) >> 5;
    int lane = threadIdx.x & 31;
    int grp = lane >> 4;
    int sub = lane & 15;
    int n = warp * 2 + grp;
    if (n >= N) return;

    const uint2* Hr = (const uint2*)Hh;
    uint2 raw = __ldg(&Hr[n * 16 + sub]);
    __half2 h0 = *reinterpret_cast<__half2*>(&raw.x);
    __half2 h1 = *reinterpret_cast<__half2*>(&raw.y);
    float2 p0 = __half22float2(h0), p1 = __half22float2(h1);
    float ax0 = p0.x, ay0 = p0.y, az0 = p1.x, aw0 = p1.y;
    float ax1 = 0.f, ay1 = 0.f, az1 = 0.f, aw1 = 0.f;

    int j = __ldg(&rowptr[n]);
    int end = __ldg(&rowptr[n + 1]);
    for (; j + 2 <= end; j += 2) {
        int s0 = __ldg(&csr[j]);
        int s1 = __ldg(&csr[j + 1]);
        uint2 r0 = __ldg(&Hr[s0 * 16 + sub]);
        uint2 r1 = __ldg(&Hr[s1 * 16 + sub]);
        float2 v00 = __half22float2(*reinterpret_cast<__half2*>(&r0.x));
        float2 v01 = __half22float2(*reinterpret_cast<__half2*>(&r0.y));
        float2 v10 = __half22float2(*reinterpret_cast<__half2*>(&r1.x));
        float2 v11 = __half22float2(*reinterpret_cast<__half2*>(&r1.y));
        ax0 += v00.x; ay0 += v00.y; az0 += v01.x; aw0 += v01.y;
        ax1 += v10.x; ay1 += v10.y; az1 += v11.x; aw1 += v11.y;
    }
    if (j < end) {
        int s0 = __ldg(&csr[j]);
        uint2 r0 = __ldg(&Hr[s0 * 16 + sub]);
        float2 v00 = __half22float2(*reinterpret_cast<__half2*>(&r0.x));
        float2 v01 = __half22float2(*reinterpret_cast<__half2*>(&r0.y));
        ax0 += v00.x; ay0 += v00.y; az0 += v01.x; aw0 += v01.y;
    }

    float dd = __ldg(&dis[n]);
    float4 bb = make_float4(0.f, 0.f, 0.f, 0.f);
    if (bias) bb = ((const float4*)bias)[sub];
    out4[n * 16 + sub] = make_float4(fmaf(ax0 + ax1, dd, bb.x),
                                     fmaf(ay0 + ay1, dd, bb.y),
                                     fmaf(az0 + az1, dd, bb.z),
                                     fmaf(aw0 + aw1, dd, bb.w));
}

// ---------------------------------------------------------------------------
// BN stats: raw sum/sumsq accumulated via atomics (buffer pre-zeroed by memset).
__global__ void bn_stats(const float* __restrict__ H, float* stats, int N) {
    int tid = threadIdx.x;
    int col = tid & 63;
    int r = blockIdx.x * 4 + (tid >> 6);
    int rstride = gridDim.x * 4;
    float s = 0.0f, q = 0.0f;
    for (; r < N; r += rstride) {
        float v = H[r * HID + col];
        s += v; q += v * v;
    }
    __shared__ float sh[256], qh[256];
    sh[tid] = s; qh[tid] = q;
    __syncthreads();
    if (tid < 64) {
        float S = sh[tid] + sh[tid + 64] + sh[tid + 128] + sh[tid + 192];
        float Q = qh[tid] + qh[tid + 64] + qh[tid + 128] + qh[tid + 192];
        atomicAdd(&stats[tid], S);
        atomicAdd(&stats[64 + tid], Q);
    }
}

// Hs[n,f] = half(relu(bn(B[n,f])) * dis[n]) — BN finalize done in-block from raw sums.
__global__ void bn_relu_dis(const float* __restrict__ H, const float* __restrict__ rawstats,
                            const float* __restrict__ g, const float* __restrict__ beta,
                            const float* __restrict__ dis, __half* __restrict__ out,
                            int total, int N) {
    __shared__ float sc[64], sh[64];
    int t = threadIdx.x;
    if (t < 64) {
        float invN = 1.0f / (float)N;
        float m = rawstats[t] * invN;
        float v = rawstats[64 + t] * invN - m * m;
        float scale = g[t] * rsqrtf(v + BN_EPS);
        sc[t] = scale;
        sh[t] = beta[t] - m * scale;
    }
    __syncthreads();
    int idx = blockIdx.x * blockDim.x + t;
    if (idx >= total) return;
    int f = idx & 63;
    int n = idx >> 6;
    float y = fmaxf(fmaf(H[idx], sc[f], sh[f]), 0.0f);
    out[idx] = __float2half(y * __ldg(&dis[n]));
}

// ---------------------------------------------------------------------------
extern "C" void kernel_launch(void* const* d_in, const int* in_sizes, int n_in,
                              void* d_out, int out_size) {
    const float* x    = (const float*)d_in[0];
    const void*  ei   = d_in[1];
    const float* W1   = (const float*)d_in[2];
    const float* b1   = (const float*)d_in[3];
    const float* g1   = (const float*)d_in[4];
    const float* be1  = (const float*)d_in[5];
    const float* W2   = (const float*)d_in[6];
    const float* b2   = (const float*)d_in[7];
    const float* g2   = (const float*)d_in[8];
    const float* be2  = (const float*)d_in[9];
    const float* Wmu  = (const float*)d_in[10];
    const float* bmu  = (const float*)d_in[11];
    const float* Wls  = (const float*)d_in[12];
    const float* bls  = (const float*)d_in[13];
    float* out = (float*)d_out;

    int N = in_sizes[0] / IND;
    int E = in_sizes[1] / 2;

    float *pA, *pB, *pDis, *pStats;
    __half2* pH;
    int *pCnt, *pRow, *pCur, *pCsr, *pBs;
    cudaGetSymbolAddress((void**)&pA, g_bufA);
    cudaGetSymbolAddress((void**)&pB, g_bufB);
    cudaGetSymbolAddress((void**)&pDis, g_dis);
    cudaGetSymbolAddress((void**)&pStats, g_stats);
    cudaGetSymbolAddress((void**)&pH, g_half);
    cudaGetSymbolAddress((void**)&pCnt, g_cnt);
    cudaGetSymbolAddress((void**)&pRow, g_rowptr);
    cudaGetSymbolAddress((void**)&pCur, g_cursor);
    cudaGetSymbolAddress((void**)&pCsr, g_csr);
    cudaGetSymbolAddress((void**)&pBs, g_bsums);

    float* pStats1 = pStats;          // BN1 raw sums
    float* pStats2 = pStats + 128;    // BN2 raw sums

    int NH = N * HID;
    int nScanBlocks = (N + SCAN_BLK - 1) / SCAN_BLK;
    dim3 gThr(64, 4);
    int gemmGrid = (N + 15) / 16;
    int aggGrid = ((N + 1) / 2 * 32 + 255) / 256;   // 2 nodes/warp, 8 warps/block

    // 0. zeroing via memset nodes (replaces zero_cnt + zero_stats x2)
    cudaMemsetAsync(pCnt, 0, (size_t)N * sizeof(int));
    cudaMemsetAsync(pStats, 0, 256 * sizeof(float));

    // 1. CSR build + normalization (scan2 folded into scan3)
    hist_dst<<<(E + 255) / 256, 256>>>(ei, pCnt, E);
    scan1<<<nScanBlocks, SCAN_BLK>>>(pCnt, pRow, pBs, N);
    scan3<<<(N + 255) / 256, 256>>>(pRow, pCur, pBs, pCnt, pDis, N, nScanBlocks);
    scatter_csr<<<(E + 255) / 256, 256>>>(ei, pCur, pCsr, E);

    // 2. conv1
    gemm81_dis<<<gemmGrid, gThr>>>(x, W1, pDis, (__half*)pH, N);
    aggregate_h2<<<aggGrid, 256>>>(pH, pRow, pCsr, pDis, b1, (float4*)pB, N);

    // 3. BN1 raw stats (finalize fused into gemm64)
    bn_stats<<<512, 256>>>(pB, pStats1, N);

    // 4. conv2 (BN1 finalize+apply+ReLU fused into GEMM input)
    gemm64_bn_dis<<<gemmGrid, gThr>>>(pB, W2, pStats1, g1, be1, pDis, (__half*)pH, N);
    aggregate_h2<<<aggGrid, 256>>>(pH, pRow, pCsr, pDis, b2, (float4*)pA, N);

    // 5. BN2 raw stats (finalize fused into bn_relu_dis)
    bn_stats<<<512, 256>>>(pA, pStats2, N);

    // 6. Hs = relu(bn(A)) * dis ; shared aggregation for both heads
    bn_relu_dis<<<(NH + 255) / 256, 256>>>(pA, pStats2, g2, be2, pDis, (__half*)pH, NH, N);
    aggregate_h2<<<aggGrid, 256>>>(pH, pRow, pCsr, pDis, (const float*)nullptr, (float4*)pB, N);

    // 7. heads
    gemm_mu_ls<<<gemmGrid, gThr>>>(pB, Wmu, bmu, Wls, bls, out, N);
}